// round 6
// baseline (speedup 1.0000x reference)
#include <cuda_runtime.h>
#include <cstdint>

// LogicGatedSNN: spikes = (membrane + x · (states > 50)^T + noise) >= threshold
// x: [8192] fp32 binary, states: [8192, 8192] fp32, out: [8192] fp32
//
// DRAM-bound 256 MiB single-pass stream. x packed once into a 1KiB bitmask
// (1 LDG.32 per thread in the main kernel). 2 rows per CTA: 16 independent
// LDG.128 fronted per thread, fixed per-row overhead (reduction chain, bar,
// epilogue) amortized over 2 rows; the two SHFL reduction chains interleave.

#define IN_F   8192
#define OUT_F  8192
#define NTHR   256
#define ROWS   2
#define VEC_PER_THREAD (IN_F / 4 / NTHR)   // 8 float4 per thread per row

// Packed x: word t holds bits for thread-slot t's 32 columns.
// bit (4*j + c) = x[4*(j*NTHR + t) + c] != 0
__device__ unsigned g_xbits[NTHR];

__global__ __launch_bounds__(NTHR) void pack_x_kernel(const float* __restrict__ x)
{
    const int tid = threadIdx.x;
    const float4* __restrict__ x4 = reinterpret_cast<const float4*>(x);
    unsigned w = 0;
    #pragma unroll
    for (int j = 0; j < VEC_PER_THREAD; ++j) {
        const float4 v = x4[j * NTHR + tid];
        unsigned nib = (v.x != 0.0f ? 1u : 0u)
                     | (v.y != 0.0f ? 2u : 0u)
                     | (v.z != 0.0f ? 4u : 0u)
                     | (v.w != 0.0f ? 8u : 0u);
        w |= nib << (4 * j);
    }
    g_xbits[tid] = w;
}

__global__ __launch_bounds__(NTHR) void snn_bits2_kernel(
    const float* __restrict__ states,   // [OUT_F, IN_F]
    const float* __restrict__ mem,      // [OUT_F]
    const float* __restrict__ thr,      // [OUT_F]
    const float* __restrict__ noise,    // [OUT_F]
    float* __restrict__ out)            // [OUT_F]
{
    __shared__ int wsum[ROWS][NTHR / 32];

    const int tid  = threadIdx.x;
    const int row0 = blockIdx.x * ROWS;

    const float4* __restrict__ s4 =
        reinterpret_cast<const float4*>(states + (size_t)row0 * IN_F);

    // 16 independent streaming LDG.128 per thread (both rows batched)
    float4 s[ROWS][VEC_PER_THREAD];
    #pragma unroll
    for (int r = 0; r < ROWS; ++r)
        #pragma unroll
        for (int j = 0; j < VEC_PER_THREAD; ++j)
            s[r][j] = __ldcs(&s4[(size_t)r * (IN_F / 4) + j * NTHR + tid]);

    const unsigned X = g_xbits[tid];     // 1KiB total, L1-hot

    int cnt[ROWS];
    #pragma unroll
    for (int r = 0; r < ROWS; ++r) {
        int c = 0;
        #pragma unroll
        for (int j = 0; j < VEC_PER_THREAD; ++j) {
            const unsigned nib = X >> (4 * j);
            c += (s[r][j].x > 50.0f) & (int)(nib & 1u);
            c += (s[r][j].y > 50.0f) & (int)((nib >> 1) & 1u);
            c += (s[r][j].z > 50.0f) & (int)((nib >> 2) & 1u);
            c += (s[r][j].w > 50.0f) & (int)((nib >> 3) & 1u);
        }
        cnt[r] = c;
    }

    // Two independent warp-reduction chains (interleave in the scheduler)
    #pragma unroll
    for (int off = 16; off > 0; off >>= 1) {
        #pragma unroll
        for (int r = 0; r < ROWS; ++r)
            cnt[r] += __shfl_xor_sync(0xffffffffu, cnt[r], off);
    }

    if ((tid & 31) == 0) {
        #pragma unroll
        for (int r = 0; r < ROWS; ++r)
            wsum[r][tid >> 5] = cnt[r];
    }
    __syncthreads();

    if (tid < ROWS) {
        int c = 0;
        #pragma unroll
        for (int w = 0; w < NTHR / 32; ++w)
            c += wsum[tid][w];
        const int row = row0 + tid;
        const float p = mem[row] + (float)c + noise[row];
        out[row] = (p >= thr[row]) ? 1.0f : 0.0f;
    }
}

extern "C" void kernel_launch(void* const* d_in, const int* in_sizes, int n_in,
                              void* d_out, int out_size) {
    const float* x      = (const float*)d_in[0];  // spike_input [1, 8192]
    const float* states = (const float*)d_in[1];  // synapse_states [8192, 8192]
    const float* mem    = (const float*)d_in[2];  // membrane_potential [8192]
    const float* thr    = (const float*)d_in[3];  // adaptive_threshold [8192]
    const float* noise  = (const float*)d_in[4];  // noise [8192]
    float* out = (float*)d_out;                   // spikes [8192]

    pack_x_kernel<<<1, NTHR>>>(x);
    snn_bits2_kernel<<<OUT_F / ROWS, NTHR>>>(states, mem, thr, noise, out);
}